// round 16
// baseline (speedup 1.0000x reference)
#include <cuda_runtime.h>
#include <cuda_bf16.h>

#define BB 2
#define NNP 8192
#define CC 64
#define HH 128
#define KC 64
#define KF 16
#define NSAMP 2048
#define NCURV 1024

__device__ float    g_t[BB * NNP * HH];
__device__ float4   g_sp[BB * NNP];
__device__ int      g_cand[BB * NNP * KC];
__device__ int      g_fidx[BB * NNP * KF];
__device__ double   g_cov[BB * NNP * 8];
__device__ double   g_curv[BB * NNP];
__device__ double   g_fvar[BB * NNP];
__device__ double   g_stats[BB * 4];
__device__ unsigned g_far_bits;
__device__ int      g_sel[BB * NSAMP];
__device__ float    g_masked[BB * NNP * 3];

__device__ __forceinline__ unsigned fmap_asc(float s) {
    unsigned u = __float_as_uint(s);
    return (u & 0x80000000u) ? ~u : (u | 0x80000000u);
}
__device__ __forceinline__ float unmap_asc(unsigned k) {
    return (k & 0x80000000u) ? __uint_as_float(k & 0x7FFFFFFFu)
                             : __uint_as_float(~k);
}
__device__ __forceinline__ float geluf(float x) {
    return 0.5f * x * (1.0f + erff(x * 0.70710678118654752440f));
}
__device__ __forceinline__ unsigned long long umin64(unsigned long long a, unsigned long long b) {
    return a < b ? a : b;
}
__device__ __forceinline__ unsigned long long umax64(unsigned long long a, unsigned long long b) {
    return a > b ? a : b;
}
// packed f32x2 helpers (per-lane bitwise-identical rn semantics)
__device__ __forceinline__ unsigned long long pk2(float lo, float hi) {
    unsigned long long r;
    asm("mov.b64 %0, {%1, %2};" : "=l"(r) : "f"(lo), "f"(hi));
    return r;
}
__device__ __forceinline__ void upk2(float& lo, float& hi, unsigned long long v) {
    asm("mov.b64 {%0, %1}, %2;" : "=f"(lo), "=f"(hi) : "l"(v));
}
__device__ __forceinline__ unsigned long long add2(unsigned long long a, unsigned long long b) {
    unsigned long long r;
    asm("add.rn.f32x2 %0, %1, %2;" : "=l"(r) : "l"(a), "l"(b));
    return r;
}
__device__ __forceinline__ unsigned long long mul2(unsigned long long a, unsigned long long b) {
    unsigned long long r;
    asm("mul.rn.f32x2 %0, %1, %2;" : "=l"(r) : "l"(a), "l"(b));
    return r;
}

// ---------- 0) init: reset far accumulator ----------
__global__ void k_init() {
    if (threadIdx.x == 0) g_far_bits = 0u;
}

// ---------- 0b) prep: pack (x,y,z,|p|^2) float4 ----------
__global__ void k_prep(const float* __restrict__ xyz) {
    int i = blockIdx.x * 256 + threadIdx.x;
    if (i >= BB * NNP) return;
    float x = xyz[i * 3], y = xyz[i * 3 + 1], z = xyz[i * 3 + 2];
    float sq = __fadd_rn(__fadd_rn(__fmul_rn(x, x), __fmul_rn(y, y)), __fmul_rn(z, z));
    g_sp[i] = make_float4(x, y, z, sq);
}

// ---------- 1) t = [xyz|feat] @ W1, double accum (4 accs), w1 in smem ----------
#define TM_P 16
__global__ void k_tmat(const float* __restrict__ xyz, const float* __restrict__ feat,
                       const float* __restrict__ w1) {
    __shared__ float sw1[67 * 128];
    __shared__ float xr[TM_P][67];
    int tid = threadIdx.x;
    for (int i = tid; i < 67 * 128; i += 128) sw1[i] = w1[i];
    int n0 = blockIdx.x * TM_P;
    for (int i = tid; i < TM_P * 67; i += 128) {
        int p = i / 67, c = i % 67;
        int n = n0 + p;
        xr[p][c] = (c < 3) ? xyz[n * 3 + c] : feat[(size_t)n * CC + (c - 3)];
    }
    __syncthreads();
#pragma unroll 1
    for (int p = 0; p < TM_P; p++) {
        double a0 = 0.0, a1 = 0.0, a2 = 0.0, a3 = 0.0;
#pragma unroll 1
        for (int i = 0; i < 64; i += 4) {
            a0 += (double)xr[p][i]     * (double)sw1[i * 128 + tid];
            a1 += (double)xr[p][i + 1] * (double)sw1[(i + 1) * 128 + tid];
            a2 += (double)xr[p][i + 2] * (double)sw1[(i + 2) * 128 + tid];
            a3 += (double)xr[p][i + 3] * (double)sw1[(i + 3) * 128 + tid];
        }
        a0 += (double)xr[p][64] * (double)sw1[64 * 128 + tid];
        a1 += (double)xr[p][65] * (double)sw1[65 * 128 + tid];
        a2 += (double)xr[p][66] * (double)sw1[66 * 128 + tid];
        g_t[(size_t)(n0 + p) * HH + tid] = (float)((a0 + a1) + (a2 + a3));
    }
}

// ---------- 2) kNN: warp-per-row streaming select, float4 smem ----------
#define KW 16
#define BUFSZ 128

__device__ __forceinline__ void wsort128(unsigned long long v[4], int lane) {
#define CE_LOC(A, B, ASC) { unsigned long long lo_ = umin64(v[A], v[B]); \
    unsigned long long hi_ = umax64(v[A], v[B]); \
    if (ASC) { v[A] = lo_; v[B] = hi_; } else { v[A] = hi_; v[B] = lo_; } }
#pragma unroll
    for (int k = 2; k <= 128; k <<= 1) {
#pragma unroll
        for (int j = 64; j > 0; j >>= 1) {
            if (j >= k) continue;
            if (j >= 4) {
                int lm = j >> 2;
#pragma unroll
                for (int r = 0; r < 4; r++) {
                    unsigned long long p = __shfl_xor_sync(0xffffffffu, v[r], lm);
                    int idx = lane * 4 + r;
                    bool tm = ((idx & k) == 0) == ((idx & j) == 0);
                    unsigned long long mn = umin64(v[r], p), mx = umax64(v[r], p);
                    v[r] = tm ? mn : mx;
                }
            } else if (j == 2) {
                bool a = (((lane * 4) & k) == 0);
                CE_LOC(0, 2, a); CE_LOC(1, 3, a);
            } else {
                if (k == 2) { CE_LOC(0, 1, true); CE_LOC(2, 3, false); }
                else { bool a = (((lane * 4) & k) == 0); CE_LOC(0, 1, a); CE_LOC(2, 3, a); }
            }
        }
    }
#undef CE_LOC
}

__global__ void k_knn(const float* __restrict__ xyz) {
    extern __shared__ char dsm[];
    unsigned long long* bufall = (unsigned long long*)dsm;       // KW*128 u64 = 16KB
    float4* sp = (float4*)(dsm + KW * BUFSZ * 8);                // NNP float4 = 128KB

    int tid = threadIdx.x, w = tid >> 5, lane = tid & 31;
    int b  = blockIdx.x >> 9;
    int wb = blockIdx.x & 511;
    int n  = wb * KW + w;
    const float4* SP = g_sp + (size_t)b * NNP;

    for (int m = tid; m < NNP; m += 512) sp[m] = SP[m];
    __syncthreads();

    unsigned long long* wbuf = bufall + w * BUFSZ;
    float4 c = sp[n];
    float tauf = __int_as_float(0x7F800000);
    unsigned long long v[4];
    int cnt = 0;

    for (int m0 = 0; m0 < NNP; m0 += 32) {
        int m = m0 + lane;
        float4 p = sp[m];
        float dot = fmaf(p.z, c.z, fmaf(p.y, c.y, __fmul_rn(p.x, c.x)));
        float d2 = __fsub_rn(__fadd_rn(c.w, p.w), __fmul_rn(2.0f, dot));
        bool ok = (m != n) && (d2 <= tauf);
        unsigned msk = __ballot_sync(0xffffffffu, ok);
        if (ok) {
            int pos = cnt + __popc(msk & ((1u << lane) - 1u));
            wbuf[pos] = (((unsigned long long)fmap_asc(d2)) << 13) | (unsigned)m;
        }
        cnt += __popc(msk);
        if (cnt > BUFSZ - 32) {
            __syncwarp();
#pragma unroll
            for (int r = 0; r < 4; r++) {
                int q = lane * 4 + r;
                v[r] = (q < cnt) ? wbuf[q] : 0xFFFFFFFFFFFFFFFFULL;
            }
            wsort128(v, lane);
            if (lane < 16) {
#pragma unroll
                for (int r = 0; r < 4; r++) wbuf[lane * 4 + r] = v[r];
            }
            unsigned long long tau = __shfl_sync(0xffffffffu, v[3], 15);
            tauf = unmap_asc((unsigned)(tau >> 13));
            cnt = 64;
            __syncwarp();
        }
    }
    __syncwarp();
#pragma unroll
    for (int r = 0; r < 4; r++) {
        int q = lane * 4 + r;
        v[r] = (q < cnt) ? wbuf[q] : 0xFFFFFFFFFFFFFFFFULL;
    }
    wsort128(v, lane);
    if (lane < 16) {
#pragma unroll
        for (int r = 0; r < 4; r++)
            g_cand[((size_t)(b * NNP + n)) * KC + lane * 4 + r] = (int)(v[r] & 8191ULL);
    }
}

// ---------- 3) scores + top-16 ----------
__global__ void k_score(const float* __restrict__ b1, const float* __restrict__ w2,
                        const float* __restrict__ b2) {
    __shared__ float sc[8][64];
    int w = threadIdx.x >> 5, lane = threadIdx.x & 31;
    int gw = blockIdx.x * 8 + w;
    int b = gw >> 13;
    const float4 tn  = *(const float4*)&g_t[(size_t)gw * HH + lane * 4];
    const float4 b14 = *(const float4*)&b1[lane * 4];
    const float4 w24 = *(const float4*)&w2[lane * 4];
    float b2v = b2[0];
    const int* cd = &g_cand[(size_t)gw * KC];

    for (int k = 0; k < KC; k++) {
        int idx = cd[k];
        const float4 tk = *(const float4*)&g_t[((size_t)(b * NNP + idx)) * HH + lane * 4];
        float p;
        p  = geluf(tk.x - tn.x + b14.x) * w24.x;
        p += geluf(tk.y - tn.y + b14.y) * w24.y;
        p += geluf(tk.z - tn.z + b14.z) * w24.z;
        p += geluf(tk.w - tn.w + b14.w) * w24.w;
        for (int o = 16; o > 0; o >>= 1) p += __shfl_xor_sync(0xffffffffu, p, o);
        if (lane == 0) sc[w][k] = p + b2v;
    }
    __syncwarp();

    unsigned long long k0 = (((unsigned long long)fmap_asc(sc[w][lane]))      << 6) | (unsigned)(63 - lane);
    unsigned long long k1 = (((unsigned long long)fmap_asc(sc[w][lane + 32])) << 6) | (unsigned)(31 - lane);
    int* fo = &g_fidx[(size_t)gw * KF];
    for (int it = 0; it < KF; it++) {
        unsigned long long vv = umax64(k0, k1);
        unsigned long long wm = vv;
        for (int o = 16; o > 0; o >>= 1) {
            unsigned long long ov = __shfl_xor_sync(0xffffffffu, wm, o);
            if (ov > wm) wm = ov;
        }
        unsigned msk = __ballot_sync(0xffffffffu, vv == wm);
        int WL = __ffs(msk) - 1;
        if (lane == WL) {
            int kk = 63 - (int)(wm & 63ULL);
            fo[it] = cd[kk];
            if (k0 == wm) k0 = 0ULL; else k1 = 0ULL;
        }
    }
}

// ---------- 4a) cov sums + feat_var, all 32 lanes ----------
__global__ void k_geomA(const float* __restrict__ xyz, const float* __restrict__ feat) {
    int w = threadIdx.x >> 5, lane = threadIdx.x & 31;
    int gw = blockIdx.x * 8 + w;
    int b = gw >> 13, n = gw & 8191;
    const float* X = xyz + (size_t)b * NNP * 3;
    const float* F = feat + (size_t)b * NNP * CC;

    int nb = lane & 15;
    int half = lane >> 4;
    int idx = g_fidx[(size_t)gw * KF + nb];

    const float4* fk = (const float4*)&F[(size_t)idx * CC] + half * 8;
    const float4* fn = (const float4*)&F[(size_t)n * CC] + half * 8;
    double ssq = 0;
#pragma unroll
    for (int cch = 0; cch < 8; cch++) {
        float4 a = fk[cch], e = fn[cch];
        float d0 = a.x - e.x, d1 = a.y - e.y, d2 = a.z - e.z, d3 = a.w - e.w;
        ssq += (double)d0 * d0 + (double)d1 * d1 + (double)d2 * d2 + (double)d3 * d3;
    }
    double other = __shfl_down_sync(0xffffffffu, ssq, 16);
    double nrm = 0;
    double sxx = 0, sxy = 0, sxz = 0, syy = 0, syz = 0, szz = 0;
    if (lane < 16) {
        nrm = sqrt(ssq + other);
        float cxn = X[n * 3], cyn = X[n * 3 + 1], czn = X[n * 3 + 2];
        float dx = X[idx * 3] - cxn, dy = X[idx * 3 + 1] - cyn, dz = X[idx * 3 + 2] - czn;
        double ddx = dx, ddy = dy, ddz = dz;
        sxx = ddx * ddx; sxy = ddx * ddy; sxz = ddx * ddz;
        syy = ddy * ddy; syz = ddy * ddz; szz = ddz * ddz;
    }
    for (int o = 8; o > 0; o >>= 1) {
        sxx += __shfl_xor_sync(0xffffffffu, sxx, o);
        sxy += __shfl_xor_sync(0xffffffffu, sxy, o);
        sxz += __shfl_xor_sync(0xffffffffu, sxz, o);
        syy += __shfl_xor_sync(0xffffffffu, syy, o);
        syz += __shfl_xor_sync(0xffffffffu, syz, o);
        szz += __shfl_xor_sync(0xffffffffu, szz, o);
        nrm += __shfl_xor_sync(0xffffffffu, nrm, o);
    }
    if (lane == 0) {
        double* cv = &g_cov[(size_t)gw * 8];
        cv[0] = sxx; cv[1] = sxy; cv[2] = sxz;
        cv[3] = syy; cv[4] = syz; cv[5] = szz;
        cv[6] = nrm;
    }
}

// ---------- 4b) eigen / curvature (thread per point) ----------
__global__ void k_geomB() {
    int gw = blockIdx.x * 256 + threadIdx.x;
    if (gw >= BB * NNP) return;
    const double* cv = &g_cov[(size_t)gw * 8];
    double a00 = cv[0] / 16.0, a01 = cv[1] / 16.0, a02 = cv[2] / 16.0;
    double a11 = cv[3] / 16.0, a12 = cv[4] / 16.0, a22 = cv[5] / 16.0;
    double q = (a00 + a11 + a22) / 3.0;
    double p1 = a01 * a01 + a02 * a02 + a12 * a12;
    double b00 = a00 - q, b11 = a11 - q, b22 = a22 - q;
    double p2 = b00 * b00 + b11 * b11 + b22 * b22 + 2.0 * p1;
    double e0, e1, e2;
    if (p2 < 1e-300) { e0 = e1 = e2 = q; }
    else {
        double p = sqrt(p2 / 6.0);
        double c00 = b00 / p, c01 = a01 / p, c02 = a02 / p;
        double c11 = b11 / p, c12 = a12 / p, c22 = b22 / p;
        double detB = c00 * (c11 * c22 - c12 * c12)
                    - c01 * (c01 * c22 - c12 * c02)
                    + c02 * (c01 * c12 - c11 * c02);
        double r = detB / 2.0;
        r = fmin(1.0, fmax(-1.0, r));
        double phi = acos(r) / 3.0;
        e0 = q + 2.0 * p * cos(phi);
        e2 = q + 2.0 * p * cos(phi + 2.0943951023931954923);
        e1 = 3.0 * q - e0 - e2;
    }
    double s0 = fabs(e0), s1 = fabs(e1), s2 = fabs(e2), tmp;
    if (s0 < s1) { tmp = s0; s0 = s1; s1 = tmp; }
    if (s1 < s2) { tmp = s1; s1 = s2; s2 = tmp; }
    if (s0 < s1) { tmp = s0; s0 = s1; s1 = tmp; }
    double l2 = s0 * s0, l1 = s1 * s1, l0 = s2 * s2;
    g_curv[gw] = l0 / (l0 + l1 + l2 + 1e-8);
    g_fvar[gw] = cv[6] / (double)KF;
}

// ---------- 5) stats + global far ----------
__device__ __forceinline__ double blockSumD(double v, double* sh) {
    int lane = threadIdx.x & 31, wid = threadIdx.x >> 5;
    for (int o = 16; o > 0; o >>= 1) v += __shfl_xor_sync(0xffffffffu, v, o);
    if (lane == 0) sh[wid] = v;
    __syncthreads();
    double r = 0;
    if (wid == 0) {
        r = sh[lane];
        for (int o = 16; o > 0; o >>= 1) r += __shfl_xor_sync(0xffffffffu, r, o);
    }
    __syncthreads();
    return r;
}

__global__ void k_statsfar(const float* __restrict__ xyz) {
    __shared__ double sh[32];
    __shared__ float shf[32];
    int b = blockIdx.x, tid = threadIdx.x, lane = tid & 31, wid = tid >> 5;
    double sc = 0, sc2 = 0, sf = 0, sf2 = 0;
    for (int i = tid; i < NNP; i += 1024) {
        double c = g_curv[b * NNP + i], f = g_fvar[b * NNP + i];
        sc += c; sc2 += c * c; sf += f; sf2 += f * f;
    }
    double S1 = blockSumD(sc, sh);
    double S2 = blockSumD(sc2, sh);
    double S3 = blockSumD(sf, sh);
    double S4 = blockSumD(sf2, sh);
    if (tid == 0) {
        double mc = S1 / NNP, mf = S3 / NNP;
        double vc = (S2 - (double)NNP * mc * mc) / (NNP - 1);
        double vf = (S4 - (double)NNP * mf * mf) / (NNP - 1);
        g_stats[b * 4 + 0] = mc;
        g_stats[b * 4 + 1] = sqrt(fmax(vc, 0.0));
        g_stats[b * 4 + 2] = mf;
        g_stats[b * 4 + 3] = sqrt(fmax(vf, 0.0));
    }
    const float* X = xyz + (size_t)b * NNP * 3;
    float m = -1e38f;
    for (int i = tid; i < NNP * 3; i += 1024) m = fmaxf(m, X[i]);
    for (int o = 16; o > 0; o >>= 1) m = fmaxf(m, __shfl_xor_sync(0xffffffffu, m, o));
    if (lane == 0) shf[wid] = m;
    __syncthreads();
    if (wid == 0) {
        float r = shf[lane];
        for (int o = 16; o > 0; o >>= 1) r = fmaxf(r, __shfl_xor_sync(0xffffffffu, r, o));
        if (tid == 0) atomicMax(&g_far_bits, fmap_asc(r));
    }
}

// ---------- 6) importance + bitonic sort -> curv_idx + build masked ----------
__global__ void k_impsortmask(const float* __restrict__ xyz) {
    extern __shared__ unsigned long long keys[];
    int b = blockIdx.x, tid = threadIdx.x;
    double mc = g_stats[b * 4 + 0], sdc = g_stats[b * 4 + 1];
    double mf = g_stats[b * 4 + 2], sdf = g_stats[b * 4 + 3];
    for (int i = tid; i < NNP; i += 1024) {
        double zc = (g_curv[b * NNP + i] - mc) / (sdc + 1e-8);
        double zf = (g_fvar[b * NNP + i] - mf) / (sdf + 1e-8);
        float imp = (float)(zc + 0.5 * zf);
        unsigned long long key =
            (((unsigned long long)fmap_asc(imp)) << 13) | (unsigned)(8191 - i);
        keys[i] = ~key;
    }
    __syncthreads();
    for (int k = 2; k <= NNP; k <<= 1) {
        for (int j = k >> 1; j > 0; j >>= 1) {
            for (int t = tid; t < NNP / 2; t += 1024) {
                int i = (t << 1) - (t & (j - 1));
                int p = i | j;
                bool up = ((i & k) == 0);
                unsigned long long a = keys[i], c = keys[p];
                if ((a > c) == up) { keys[i] = c; keys[p] = a; }
            }
            __syncthreads();
        }
    }
    for (int r = tid; r < NCURV; r += 1024) {
        unsigned long long orig = ~keys[r];
        g_sel[b * NSAMP + r] = 8191 - (int)(orig & 8191ULL);
    }
    const float* X = xyz + (size_t)b * NNP * 3;
    float* M = g_masked + (size_t)b * NNP * 3;
    for (int i = tid; i < NNP * 3; i += 1024) M[i] = X[i];
    __syncthreads();
    float fv = unmap_asc(g_far_bits) + 1.0f;
    for (int r = tid; r < NCURV; r += 1024) {
        int idx = g_sel[b * NSAMP + r];
        M[idx * 3 + 0] = fv;
        M[idx * 3 + 1] = fv;
        M[idx * 3 + 2] = fv;
    }
}

// ---------- 7) FPS: f32x2 md-loop, one barrier/iter, smem u64 atomic argmax ----------
__global__ void k_fps() {
    extern __shared__ float sx[];              // NNP*3 floats
    __shared__ unsigned long long slots[3];
    int b = blockIdx.x, tid = threadIdx.x, lane = tid & 31;
    const float* M = g_masked + (size_t)b * NNP * 3;
    for (int i = tid; i < NNP * 3; i += 1024) sx[i] = M[i];
    if (tid == 0) { slots[0] = 0ULL; slots[1] = 0ULL; slots[2] = 0ULL; }
    __syncthreads();

    unsigned long long px2[4], py2[4], pz2[4];
    float md[8];
#pragma unroll
    for (int s = 0; s < 4; s++) {
        int i0 = tid * 8 + 2 * s, i1 = i0 + 1;
        px2[s] = pk2(sx[i0 * 3],     sx[i1 * 3]);
        py2[s] = pk2(sx[i0 * 3 + 1], sx[i1 * 3 + 1]);
        pz2[s] = pk2(sx[i0 * 3 + 2], sx[i1 * 3 + 2]);
        md[2 * s] = 1e10f; md[2 * s + 1] = 1e10f;
    }

    int last = 0;
    for (int it = 0; it < NCURV; it++) {
        if (tid == 0) g_sel[b * NSAMP + NCURV + it] = last;
        float lx = sx[last * 3], ly = sx[last * 3 + 1], lz = sx[last * 3 + 2];
        unsigned long long nlx = pk2(-lx, -lx), nly = pk2(-ly, -ly), nlz = pk2(-lz, -lz);
        float bv = -1.0f; int bs = 0;
#pragma unroll
        for (int s = 0; s < 4; s++) {
            // a + (-b) rounds identically to a - b
            unsigned long long dx = add2(px2[s], nlx);
            unsigned long long dy = add2(py2[s], nly);
            unsigned long long dz = add2(pz2[s], nlz);
            unsigned long long d2p = add2(add2(mul2(dx, dx), mul2(dy, dy)), mul2(dz, dz));
            float d0, d1;
            upk2(d0, d1, d2p);
            float m0 = fminf(md[2 * s], d0);
            float m1 = fminf(md[2 * s + 1], d1);
            md[2 * s] = m0; md[2 * s + 1] = m1;
            if (m0 > bv) { bv = m0; bs = 2 * s; }       // strict >: first-max kept
            if (m1 > bv) { bv = m1; bs = 2 * s + 1; }
        }
        // md >= 0: raw float bit order == float order
        unsigned mybits = __float_as_uint(bv);
        unsigned wmax = __reduce_max_sync(0xffffffffu, mybits);
        unsigned cand = (mybits == wmax) ? (unsigned)(tid * 8 + bs) : 0xFFFFFFFFu;
        unsigned widx = __reduce_min_sync(0xffffffffu, cand);
        int p = it % 3;
        if (lane == 0)
            atomicMax(&slots[p],
                      (((unsigned long long)wmax) << 13) | (unsigned)(8191 - widx));
        __syncthreads();
        unsigned long long key = slots[p];
        last = 8191 - (int)(key & 8191ULL);
        // reset slot for iteration it+2; its readers (iter it-1) are ordered
        // before this barrier, its next writers (iter it+2) after the next one.
        if (tid == 0) slots[(p + 2) % 3] = 0ULL;
    }
}

// ---------- 8) output ----------
__global__ void k_out(const float* __restrict__ xyz, float* __restrict__ out) {
    int t = blockIdx.x * 256 + threadIdx.x;
    if (t >= BB * NSAMP) return;
    int b = t >> 11;
    int idx = g_sel[t];
    const float* src = xyz + ((size_t)b * NNP + idx) * 3;
    out[t * 3 + 0] = src[0];
    out[t * 3 + 1] = src[1];
    out[t * 3 + 2] = src[2];
    out[BB * NSAMP * 3 + t] = (float)idx;
}

extern "C" void kernel_launch(void* const* d_in, const int* in_sizes, int n_in,
                              void* d_out, int out_size) {
    const float* xyz  = (const float*)d_in[0];
    const float* feat = (const float*)d_in[1];
    const float* w1   = (const float*)d_in[2];
    const float* b1   = (const float*)d_in[3];
    const float* w2   = (const float*)d_in[4];
    const float* b2   = (const float*)d_in[5];
    float* out = (float*)d_out;

    const int KNN_SMEM = KW * BUFSZ * 8 + NNP * 16;  // 147456
    cudaFuncSetAttribute(k_knn, cudaFuncAttributeMaxDynamicSharedMemorySize, KNN_SMEM);
    cudaFuncSetAttribute(k_impsortmask, cudaFuncAttributeMaxDynamicSharedMemorySize, NNP * 8);
    cudaFuncSetAttribute(k_fps, cudaFuncAttributeMaxDynamicSharedMemorySize, NNP * 3 * 4);

    k_init<<<1, 32>>>();                                       // launch 0
    k_tmat<<<BB * NNP / TM_P, 128>>>(xyz, feat, w1);           // launch 1
    k_prep<<<(BB * NNP + 255) / 256, 256>>>(xyz);              // launch 2
    k_knn<<<BB * NNP / KW, 512, KNN_SMEM>>>(xyz);              // launch 3 (profiled)
    k_score<<<BB * NNP / 8, 256>>>(b1, w2, b2);                // launch 4
    k_geomA<<<BB * NNP / 8, 256>>>(xyz, feat);                 // launch 5
    k_geomB<<<BB * NNP / 256, 256>>>();                        // launch 6
    k_statsfar<<<BB, 1024>>>(xyz);                             // launch 7
    k_impsortmask<<<BB, 1024, NNP * 8>>>(xyz);                 // launch 8
    k_fps<<<BB, 1024, NNP * 3 * 4>>>();                        // launch 9
    k_out<<<(BB * NSAMP + 255) / 256, 256>>>(xyz, out);        // launch 10
}

// round 17
// speedup vs baseline: 1.0946x; 1.0946x over previous
#include <cuda_runtime.h>
#include <cuda_bf16.h>

#define BB 2
#define NNP 8192
#define CC 64
#define HH 128
#define KC 64
#define KF 16
#define NSAMP 2048
#define NCURV 1024

__device__ float    g_t[BB * NNP * HH];
__device__ float4   g_sp[BB * NNP];
__device__ int      g_cand[BB * NNP * KC];
__device__ int      g_fidx[BB * NNP * KF];
__device__ double   g_cov[BB * NNP * 8];
__device__ double   g_curv[BB * NNP];
__device__ double   g_fvar[BB * NNP];
__device__ double   g_stats[BB * 4];
__device__ unsigned g_far_bits;
__device__ int      g_sel[BB * NSAMP];
__device__ float    g_masked[BB * NNP * 3];

__device__ __forceinline__ unsigned fmap_asc(float s) {
    unsigned u = __float_as_uint(s);
    return (u & 0x80000000u) ? ~u : (u | 0x80000000u);
}
__device__ __forceinline__ float unmap_asc(unsigned k) {
    return (k & 0x80000000u) ? __uint_as_float(k & 0x7FFFFFFFu)
                             : __uint_as_float(~k);
}
__device__ __forceinline__ float geluf(float x) {
    return 0.5f * x * (1.0f + erff(x * 0.70710678118654752440f));
}
__device__ __forceinline__ unsigned long long umin64(unsigned long long a, unsigned long long b) {
    return a < b ? a : b;
}
__device__ __forceinline__ unsigned long long umax64(unsigned long long a, unsigned long long b) {
    return a > b ? a : b;
}
// packed f32x2 helpers (per-lane bitwise-identical rn semantics)
__device__ __forceinline__ unsigned long long pk2(float lo, float hi) {
    unsigned long long r;
    asm("mov.b64 %0, {%1, %2};" : "=l"(r) : "f"(lo), "f"(hi));
    return r;
}
__device__ __forceinline__ void upk2(float& lo, float& hi, unsigned long long v) {
    asm("mov.b64 {%0, %1}, %2;" : "=f"(lo), "=f"(hi) : "l"(v));
}
__device__ __forceinline__ unsigned long long add2(unsigned long long a, unsigned long long b) {
    unsigned long long r;
    asm("add.rn.f32x2 %0, %1, %2;" : "=l"(r) : "l"(a), "l"(b));
    return r;
}
__device__ __forceinline__ unsigned long long mul2(unsigned long long a, unsigned long long b) {
    unsigned long long r;
    asm("mul.rn.f32x2 %0, %1, %2;" : "=l"(r) : "l"(a), "l"(b));
    return r;
}

// ---------- 0) init: reset far accumulator ----------
__global__ void k_init() {
    if (threadIdx.x == 0) g_far_bits = 0u;
}

// ---------- 0b) prep: pack (x,y,z,|p|^2) float4 ----------
__global__ void k_prep(const float* __restrict__ xyz) {
    int i = blockIdx.x * 256 + threadIdx.x;
    if (i >= BB * NNP) return;
    float x = xyz[i * 3], y = xyz[i * 3 + 1], z = xyz[i * 3 + 2];
    float sq = __fadd_rn(__fadd_rn(__fmul_rn(x, x), __fmul_rn(y, y)), __fmul_rn(z, z));
    g_sp[i] = make_float4(x, y, z, sq);
}

// ---------- 1) t = [xyz|feat] @ W1, double accum (4 accs), w1 in smem ----------
#define TM_P 16
__global__ void k_tmat(const float* __restrict__ xyz, const float* __restrict__ feat,
                       const float* __restrict__ w1) {
    __shared__ float sw1[67 * 128];
    __shared__ float xr[TM_P][67];
    int tid = threadIdx.x;
    for (int i = tid; i < 67 * 128; i += 128) sw1[i] = w1[i];
    int n0 = blockIdx.x * TM_P;
    for (int i = tid; i < TM_P * 67; i += 128) {
        int p = i / 67, c = i % 67;
        int n = n0 + p;
        xr[p][c] = (c < 3) ? xyz[n * 3 + c] : feat[(size_t)n * CC + (c - 3)];
    }
    __syncthreads();
#pragma unroll 1
    for (int p = 0; p < TM_P; p++) {
        double a0 = 0.0, a1 = 0.0, a2 = 0.0, a3 = 0.0;
#pragma unroll 1
        for (int i = 0; i < 64; i += 4) {
            a0 += (double)xr[p][i]     * (double)sw1[i * 128 + tid];
            a1 += (double)xr[p][i + 1] * (double)sw1[(i + 1) * 128 + tid];
            a2 += (double)xr[p][i + 2] * (double)sw1[(i + 2) * 128 + tid];
            a3 += (double)xr[p][i + 3] * (double)sw1[(i + 3) * 128 + tid];
        }
        a0 += (double)xr[p][64] * (double)sw1[64 * 128 + tid];
        a1 += (double)xr[p][65] * (double)sw1[65 * 128 + tid];
        a2 += (double)xr[p][66] * (double)sw1[66 * 128 + tid];
        g_t[(size_t)(n0 + p) * HH + tid] = (float)((a0 + a1) + (a2 + a3));
    }
}

// ---------- 2) kNN: 32 warps/block (occ 2x), warp-per-row streaming select ----------
#define KW 32
#define BUFSZ 128

__device__ __forceinline__ void wsort128(unsigned long long v[4], int lane) {
#define CE_LOC(A, B, ASC) { unsigned long long lo_ = umin64(v[A], v[B]); \
    unsigned long long hi_ = umax64(v[A], v[B]); \
    if (ASC) { v[A] = lo_; v[B] = hi_; } else { v[A] = hi_; v[B] = lo_; } }
#pragma unroll
    for (int k = 2; k <= 128; k <<= 1) {
#pragma unroll
        for (int j = 64; j > 0; j >>= 1) {
            if (j >= k) continue;
            if (j >= 4) {
                int lm = j >> 2;
#pragma unroll
                for (int r = 0; r < 4; r++) {
                    unsigned long long p = __shfl_xor_sync(0xffffffffu, v[r], lm);
                    int idx = lane * 4 + r;
                    bool tm = ((idx & k) == 0) == ((idx & j) == 0);
                    unsigned long long mn = umin64(v[r], p), mx = umax64(v[r], p);
                    v[r] = tm ? mn : mx;
                }
            } else if (j == 2) {
                bool a = (((lane * 4) & k) == 0);
                CE_LOC(0, 2, a); CE_LOC(1, 3, a);
            } else {
                if (k == 2) { CE_LOC(0, 1, true); CE_LOC(2, 3, false); }
                else { bool a = (((lane * 4) & k) == 0); CE_LOC(0, 1, a); CE_LOC(2, 3, a); }
            }
        }
    }
#undef CE_LOC
}

__global__ void k_knn(const float* __restrict__ xyz) {
    extern __shared__ char dsm[];
    unsigned long long* bufall = (unsigned long long*)dsm;       // KW*128 u64 = 32KB
    float4* sp = (float4*)(dsm + KW * BUFSZ * 8);                // NNP float4 = 128KB

    int tid = threadIdx.x, w = tid >> 5, lane = tid & 31;
    int b  = blockIdx.x >> 8;        // 256 blocks per batch
    int wb = blockIdx.x & 255;
    int n  = wb * KW + w;
    const float4* SP = g_sp + (size_t)b * NNP;

    for (int m = tid; m < NNP; m += 1024) sp[m] = SP[m];
    __syncthreads();

    unsigned long long* wbuf = bufall + w * BUFSZ;
    float4 c = sp[n];
    float tauf = __int_as_float(0x7F800000);
    unsigned long long v[4];
    int cnt = 0;

    for (int m0 = 0; m0 < NNP; m0 += 32) {
        int m = m0 + lane;
        float4 p = sp[m];
        float dot = fmaf(p.z, c.z, fmaf(p.y, c.y, __fmul_rn(p.x, c.x)));
        float d2 = __fsub_rn(__fadd_rn(c.w, p.w), __fmul_rn(2.0f, dot));
        bool ok = (m != n) && (d2 <= tauf);
        unsigned msk = __ballot_sync(0xffffffffu, ok);
        if (ok) {
            int pos = cnt + __popc(msk & ((1u << lane) - 1u));
            wbuf[pos] = (((unsigned long long)fmap_asc(d2)) << 13) | (unsigned)m;
        }
        cnt += __popc(msk);
        if (cnt > BUFSZ - 32) {
            __syncwarp();
#pragma unroll
            for (int r = 0; r < 4; r++) {
                int q = lane * 4 + r;
                v[r] = (q < cnt) ? wbuf[q] : 0xFFFFFFFFFFFFFFFFULL;
            }
            wsort128(v, lane);
            if (lane < 16) {
#pragma unroll
                for (int r = 0; r < 4; r++) wbuf[lane * 4 + r] = v[r];
            }
            unsigned long long tau = __shfl_sync(0xffffffffu, v[3], 15);
            tauf = unmap_asc((unsigned)(tau >> 13));
            cnt = 64;
            __syncwarp();
        }
    }
    __syncwarp();
#pragma unroll
    for (int r = 0; r < 4; r++) {
        int q = lane * 4 + r;
        v[r] = (q < cnt) ? wbuf[q] : 0xFFFFFFFFFFFFFFFFULL;
    }
    wsort128(v, lane);
    if (lane < 16) {
#pragma unroll
        for (int r = 0; r < 4; r++)
            g_cand[((size_t)(b * NNP + n)) * KC + lane * 4 + r] = (int)(v[r] & 8191ULL);
    }
}

// ---------- 3) scores + top-16 ----------
__global__ void k_score(const float* __restrict__ b1, const float* __restrict__ w2,
                        const float* __restrict__ b2) {
    __shared__ float sc[8][64];
    int w = threadIdx.x >> 5, lane = threadIdx.x & 31;
    int gw = blockIdx.x * 8 + w;
    int b = gw >> 13;
    const float4 tn  = *(const float4*)&g_t[(size_t)gw * HH + lane * 4];
    const float4 b14 = *(const float4*)&b1[lane * 4];
    const float4 w24 = *(const float4*)&w2[lane * 4];
    float b2v = b2[0];
    const int* cd = &g_cand[(size_t)gw * KC];

    for (int k = 0; k < KC; k++) {
        int idx = cd[k];
        const float4 tk = *(const float4*)&g_t[((size_t)(b * NNP + idx)) * HH + lane * 4];
        float p;
        p  = geluf(tk.x - tn.x + b14.x) * w24.x;
        p += geluf(tk.y - tn.y + b14.y) * w24.y;
        p += geluf(tk.z - tn.z + b14.z) * w24.z;
        p += geluf(tk.w - tn.w + b14.w) * w24.w;
        for (int o = 16; o > 0; o >>= 1) p += __shfl_xor_sync(0xffffffffu, p, o);
        if (lane == 0) sc[w][k] = p + b2v;
    }
    __syncwarp();

    unsigned long long k0 = (((unsigned long long)fmap_asc(sc[w][lane]))      << 6) | (unsigned)(63 - lane);
    unsigned long long k1 = (((unsigned long long)fmap_asc(sc[w][lane + 32])) << 6) | (unsigned)(31 - lane);
    int* fo = &g_fidx[(size_t)gw * KF];
    for (int it = 0; it < KF; it++) {
        unsigned long long vv = umax64(k0, k1);
        unsigned long long wm = vv;
        for (int o = 16; o > 0; o >>= 1) {
            unsigned long long ov = __shfl_xor_sync(0xffffffffu, wm, o);
            if (ov > wm) wm = ov;
        }
        unsigned msk = __ballot_sync(0xffffffffu, vv == wm);
        int WL = __ffs(msk) - 1;
        if (lane == WL) {
            int kk = 63 - (int)(wm & 63ULL);
            fo[it] = cd[kk];
            if (k0 == wm) k0 = 0ULL; else k1 = 0ULL;
        }
    }
}

// ---------- 4a) cov sums + feat_var, all 32 lanes ----------
__global__ void k_geomA(const float* __restrict__ xyz, const float* __restrict__ feat) {
    int w = threadIdx.x >> 5, lane = threadIdx.x & 31;
    int gw = blockIdx.x * 8 + w;
    int b = gw >> 13, n = gw & 8191;
    const float* X = xyz + (size_t)b * NNP * 3;
    const float* F = feat + (size_t)b * NNP * CC;

    int nb = lane & 15;
    int half = lane >> 4;
    int idx = g_fidx[(size_t)gw * KF + nb];

    const float4* fk = (const float4*)&F[(size_t)idx * CC] + half * 8;
    const float4* fn = (const float4*)&F[(size_t)n * CC] + half * 8;
    double ssq = 0;
#pragma unroll
    for (int cch = 0; cch < 8; cch++) {
        float4 a = fk[cch], e = fn[cch];
        float d0 = a.x - e.x, d1 = a.y - e.y, d2 = a.z - e.z, d3 = a.w - e.w;
        ssq += (double)d0 * d0 + (double)d1 * d1 + (double)d2 * d2 + (double)d3 * d3;
    }
    double other = __shfl_down_sync(0xffffffffu, ssq, 16);
    double nrm = 0;
    double sxx = 0, sxy = 0, sxz = 0, syy = 0, syz = 0, szz = 0;
    if (lane < 16) {
        nrm = sqrt(ssq + other);
        float cxn = X[n * 3], cyn = X[n * 3 + 1], czn = X[n * 3 + 2];
        float dx = X[idx * 3] - cxn, dy = X[idx * 3 + 1] - cyn, dz = X[idx * 3 + 2] - czn;
        double ddx = dx, ddy = dy, ddz = dz;
        sxx = ddx * ddx; sxy = ddx * ddy; sxz = ddx * ddz;
        syy = ddy * ddy; syz = ddy * ddz; szz = ddz * ddz;
    }
    for (int o = 8; o > 0; o >>= 1) {
        sxx += __shfl_xor_sync(0xffffffffu, sxx, o);
        sxy += __shfl_xor_sync(0xffffffffu, sxy, o);
        sxz += __shfl_xor_sync(0xffffffffu, sxz, o);
        syy += __shfl_xor_sync(0xffffffffu, syy, o);
        syz += __shfl_xor_sync(0xffffffffu, syz, o);
        szz += __shfl_xor_sync(0xffffffffu, szz, o);
        nrm += __shfl_xor_sync(0xffffffffu, nrm, o);
    }
    if (lane == 0) {
        double* cv = &g_cov[(size_t)gw * 8];
        cv[0] = sxx; cv[1] = sxy; cv[2] = sxz;
        cv[3] = syy; cv[4] = syz; cv[5] = szz;
        cv[6] = nrm;
    }
}

// ---------- 4b) eigen / curvature (thread per point) ----------
__global__ void k_geomB() {
    int gw = blockIdx.x * 256 + threadIdx.x;
    if (gw >= BB * NNP) return;
    const double* cv = &g_cov[(size_t)gw * 8];
    double a00 = cv[0] / 16.0, a01 = cv[1] / 16.0, a02 = cv[2] / 16.0;
    double a11 = cv[3] / 16.0, a12 = cv[4] / 16.0, a22 = cv[5] / 16.0;
    double q = (a00 + a11 + a22) / 3.0;
    double p1 = a01 * a01 + a02 * a02 + a12 * a12;
    double b00 = a00 - q, b11 = a11 - q, b22 = a22 - q;
    double p2 = b00 * b00 + b11 * b11 + b22 * b22 + 2.0 * p1;
    double e0, e1, e2;
    if (p2 < 1e-300) { e0 = e1 = e2 = q; }
    else {
        double p = sqrt(p2 / 6.0);
        double c00 = b00 / p, c01 = a01 / p, c02 = a02 / p;
        double c11 = b11 / p, c12 = a12 / p, c22 = b22 / p;
        double detB = c00 * (c11 * c22 - c12 * c12)
                    - c01 * (c01 * c22 - c12 * c02)
                    + c02 * (c01 * c12 - c11 * c02);
        double r = detB / 2.0;
        r = fmin(1.0, fmax(-1.0, r));
        double phi = acos(r) / 3.0;
        e0 = q + 2.0 * p * cos(phi);
        e2 = q + 2.0 * p * cos(phi + 2.0943951023931954923);
        e1 = 3.0 * q - e0 - e2;
    }
    double s0 = fabs(e0), s1 = fabs(e1), s2 = fabs(e2), tmp;
    if (s0 < s1) { tmp = s0; s0 = s1; s1 = tmp; }
    if (s1 < s2) { tmp = s1; s1 = s2; s2 = tmp; }
    if (s0 < s1) { tmp = s0; s0 = s1; s1 = tmp; }
    double l2 = s0 * s0, l1 = s1 * s1, l0 = s2 * s2;
    g_curv[gw] = l0 / (l0 + l1 + l2 + 1e-8);
    g_fvar[gw] = cv[6] / (double)KF;
}

// ---------- 5) stats + global far ----------
__device__ __forceinline__ double blockSumD(double v, double* sh) {
    int lane = threadIdx.x & 31, wid = threadIdx.x >> 5;
    for (int o = 16; o > 0; o >>= 1) v += __shfl_xor_sync(0xffffffffu, v, o);
    if (lane == 0) sh[wid] = v;
    __syncthreads();
    double r = 0;
    if (wid == 0) {
        r = sh[lane];
        for (int o = 16; o > 0; o >>= 1) r += __shfl_xor_sync(0xffffffffu, r, o);
    }
    __syncthreads();
    return r;
}

__global__ void k_statsfar(const float* __restrict__ xyz) {
    __shared__ double sh[32];
    __shared__ float shf[32];
    int b = blockIdx.x, tid = threadIdx.x, lane = tid & 31, wid = tid >> 5;
    double sc = 0, sc2 = 0, sf = 0, sf2 = 0;
    for (int i = tid; i < NNP; i += 1024) {
        double c = g_curv[b * NNP + i], f = g_fvar[b * NNP + i];
        sc += c; sc2 += c * c; sf += f; sf2 += f * f;
    }
    double S1 = blockSumD(sc, sh);
    double S2 = blockSumD(sc2, sh);
    double S3 = blockSumD(sf, sh);
    double S4 = blockSumD(sf2, sh);
    if (tid == 0) {
        double mc = S1 / NNP, mf = S3 / NNP;
        double vc = (S2 - (double)NNP * mc * mc) / (NNP - 1);
        double vf = (S4 - (double)NNP * mf * mf) / (NNP - 1);
        g_stats[b * 4 + 0] = mc;
        g_stats[b * 4 + 1] = sqrt(fmax(vc, 0.0));
        g_stats[b * 4 + 2] = mf;
        g_stats[b * 4 + 3] = sqrt(fmax(vf, 0.0));
    }
    const float* X = xyz + (size_t)b * NNP * 3;
    float m = -1e38f;
    for (int i = tid; i < NNP * 3; i += 1024) m = fmaxf(m, X[i]);
    for (int o = 16; o > 0; o >>= 1) m = fmaxf(m, __shfl_xor_sync(0xffffffffu, m, o));
    if (lane == 0) shf[wid] = m;
    __syncthreads();
    if (wid == 0) {
        float r = shf[lane];
        for (int o = 16; o > 0; o >>= 1) r = fmaxf(r, __shfl_xor_sync(0xffffffffu, r, o));
        if (tid == 0) atomicMax(&g_far_bits, fmap_asc(r));
    }
}

// ---------- 6) importance + bitonic sort -> curv_idx + build masked ----------
__global__ void k_impsortmask(const float* __restrict__ xyz) {
    extern __shared__ unsigned long long keys[];
    int b = blockIdx.x, tid = threadIdx.x;
    double mc = g_stats[b * 4 + 0], sdc = g_stats[b * 4 + 1];
    double mf = g_stats[b * 4 + 2], sdf = g_stats[b * 4 + 3];
    for (int i = tid; i < NNP; i += 1024) {
        double zc = (g_curv[b * NNP + i] - mc) / (sdc + 1e-8);
        double zf = (g_fvar[b * NNP + i] - mf) / (sdf + 1e-8);
        float imp = (float)(zc + 0.5 * zf);
        unsigned long long key =
            (((unsigned long long)fmap_asc(imp)) << 13) | (unsigned)(8191 - i);
        keys[i] = ~key;
    }
    __syncthreads();
    for (int k = 2; k <= NNP; k <<= 1) {
        for (int j = k >> 1; j > 0; j >>= 1) {
            for (int t = tid; t < NNP / 2; t += 1024) {
                int i = (t << 1) - (t & (j - 1));
                int p = i | j;
                bool up = ((i & k) == 0);
                unsigned long long a = keys[i], c = keys[p];
                if ((a > c) == up) { keys[i] = c; keys[p] = a; }
            }
            __syncthreads();
        }
    }
    for (int r = tid; r < NCURV; r += 1024) {
        unsigned long long orig = ~keys[r];
        g_sel[b * NSAMP + r] = 8191 - (int)(orig & 8191ULL);
    }
    const float* X = xyz + (size_t)b * NNP * 3;
    float* M = g_masked + (size_t)b * NNP * 3;
    for (int i = tid; i < NNP * 3; i += 1024) M[i] = X[i];
    __syncthreads();
    float fv = unmap_asc(g_far_bits) + 1.0f;
    for (int r = tid; r < NCURV; r += 1024) {
        int idx = g_sel[b * NSAMP + r];
        M[idx * 3 + 0] = fv;
        M[idx * 3 + 1] = fv;
        M[idx * 3 + 2] = fv;
    }
}

// ---------- 7) FPS: f32x2 md-loop, 1 barrier/iter, double-buffered REDUX argmax ----------
__global__ void k_fps() {
    extern __shared__ float sx[];              // NNP*3 floats
    __shared__ unsigned su[2][32];
    __shared__ unsigned si[2][32];
    int b = blockIdx.x, tid = threadIdx.x, lane = tid & 31, wid = tid >> 5;
    const float* M = g_masked + (size_t)b * NNP * 3;
    for (int i = tid; i < NNP * 3; i += 1024) sx[i] = M[i];
    __syncthreads();

    unsigned long long px2[4], py2[4], pz2[4];
    float md[8];
#pragma unroll
    for (int s = 0; s < 4; s++) {
        int i0 = tid * 8 + 2 * s, i1 = i0 + 1;
        px2[s] = pk2(sx[i0 * 3],     sx[i1 * 3]);
        py2[s] = pk2(sx[i0 * 3 + 1], sx[i1 * 3 + 1]);
        pz2[s] = pk2(sx[i0 * 3 + 2], sx[i1 * 3 + 2]);
        md[2 * s] = 1e10f; md[2 * s + 1] = 1e10f;
    }

    int last = 0;
    for (int it = 0; it < NCURV; it++) {
        if (tid == 0) g_sel[b * NSAMP + NCURV + it] = last;
        float lx = sx[last * 3], ly = sx[last * 3 + 1], lz = sx[last * 3 + 2];
        unsigned long long nlx = pk2(-lx, -lx), nly = pk2(-ly, -ly), nlz = pk2(-lz, -lz);
        float bv = -1.0f; int bs = 0;
#pragma unroll
        for (int s = 0; s < 4; s++) {
            // a + (-b) rounds identically to a - b
            unsigned long long dx = add2(px2[s], nlx);
            unsigned long long dy = add2(py2[s], nly);
            unsigned long long dz = add2(pz2[s], nlz);
            unsigned long long d2p = add2(add2(mul2(dx, dx), mul2(dy, dy)), mul2(dz, dz));
            float d0, d1;
            upk2(d0, d1, d2p);
            float m0 = fminf(md[2 * s], d0);
            float m1 = fminf(md[2 * s + 1], d1);
            md[2 * s] = m0; md[2 * s + 1] = m1;
            if (m0 > bv) { bv = m0; bs = 2 * s; }       // strict >: first-max kept
            if (m1 > bv) { bv = m1; bs = 2 * s + 1; }
        }
        // md >= 0: raw float bit order == float order
        unsigned mybits = __float_as_uint(bv);
        unsigned wmax = __reduce_max_sync(0xffffffffu, mybits);
        unsigned cand = (mybits == wmax) ? (unsigned)(tid * 8 + bs) : 0xFFFFFFFFu;
        unsigned widx = __reduce_min_sync(0xffffffffu, cand);
        int p = it & 1;
        if (lane == 0) { su[p][wid] = wmax; si[p][wid] = widx; }
        __syncthreads();
        // every warp reduces the 32 per-warp winners redundantly (no 2nd barrier;
        // double buffer p makes iter i+2's writes safe vs iter i's reads)
        unsigned vb = su[p][lane], vi = si[p][lane];
        unsigned bmax = __reduce_max_sync(0xffffffffu, vb);
        unsigned c2 = (vb == bmax) ? vi : 0xFFFFFFFFu;
        last = (int)__reduce_min_sync(0xffffffffu, c2);
    }
}

// ---------- 8) output ----------
__global__ void k_out(const float* __restrict__ xyz, float* __restrict__ out) {
    int t = blockIdx.x * 256 + threadIdx.x;
    if (t >= BB * NSAMP) return;
    int b = t >> 11;
    int idx = g_sel[t];
    const float* src = xyz + ((size_t)b * NNP + idx) * 3;
    out[t * 3 + 0] = src[0];
    out[t * 3 + 1] = src[1];
    out[t * 3 + 2] = src[2];
    out[BB * NSAMP * 3 + t] = (float)idx;
}

extern "C" void kernel_launch(void* const* d_in, const int* in_sizes, int n_in,
                              void* d_out, int out_size) {
    const float* xyz  = (const float*)d_in[0];
    const float* feat = (const float*)d_in[1];
    const float* w1   = (const float*)d_in[2];
    const float* b1   = (const float*)d_in[3];
    const float* w2   = (const float*)d_in[4];
    const float* b2   = (const float*)d_in[5];
    float* out = (float*)d_out;

    const int KNN_SMEM = KW * BUFSZ * 8 + NNP * 16;  // 32KB + 128KB = 163840
    cudaFuncSetAttribute(k_knn, cudaFuncAttributeMaxDynamicSharedMemorySize, KNN_SMEM);
    cudaFuncSetAttribute(k_impsortmask, cudaFuncAttributeMaxDynamicSharedMemorySize, NNP * 8);
    cudaFuncSetAttribute(k_fps, cudaFuncAttributeMaxDynamicSharedMemorySize, NNP * 3 * 4);

    k_init<<<1, 32>>>();                                       // launch 0
    k_tmat<<<BB * NNP / TM_P, 128>>>(xyz, feat, w1);           // launch 1
    k_prep<<<(BB * NNP + 255) / 256, 256>>>(xyz);              // launch 2
    k_knn<<<BB * (NNP / KW), 1024, KNN_SMEM>>>(xyz);           // launch 3 (profiled)
    k_score<<<BB * NNP / 8, 256>>>(b1, w2, b2);                // launch 4
    k_geomA<<<BB * NNP / 8, 256>>>(xyz, feat);                 // launch 5
    k_geomB<<<BB * NNP / 256, 256>>>();                        // launch 6
    k_statsfar<<<BB, 1024>>>(xyz);                             // launch 7
    k_impsortmask<<<BB, 1024, NNP * 8>>>(xyz);                 // launch 8
    k_fps<<<BB, 1024, NNP * 3 * 4>>>();                        // launch 9
    k_out<<<(BB * NSAMP + 255) / 256, 256>>>(xyz, out);        // launch 10
}